// round 13
// baseline (speedup 1.0000x reference)
#include <cuda_runtime.h>
#include <cuda_bf16.h>
#include <cuda_fp16.h>
#include <cstdint>

// ---------------- problem constants ----------------
#define N_MAX 100000
#define E_MAX 1600000
#define IN_DIM 128
#define HID_DIM 128
#define OUT_DIM 64

typedef unsigned long long u64;

// ---------------- device scratch ----------------
__device__ int   g_cnt[N_MAX];
__device__ int   g_rptr[N_MAX + 1];
__device__ int   g_cursor[N_MAX];
__device__ int   g_part[256];
__device__ float g_dinv[N_MAX];
__device__ int   g_csr[E_MAX];
// fp16 message/feature buffers
__device__ __align__(16) __half g_g1[(size_t)N_MAX * HID_DIM];
__device__ __align__(16) __half g_h1[(size_t)N_MAX * HID_DIM];
__device__ __align__(16) __half g_g2[(size_t)N_MAX * OUT_DIM];
// W1 and W2 pre-split fp16 hi/lo, layout Wt[c][k] (k contiguous), hi block then lo
__device__ __align__(16) __half g_w1s[2 * HID_DIM * IN_DIM];
__device__ __align__(16) __half g_w2s[2 * OUT_DIM * HID_DIM];

// ---------------- PTX helpers (baseline ISA: ldmatrix + mma.sync) ----------
__device__ __forceinline__ uint32_t smem_u32(const void* p) {
    uint32_t a;
    asm("{ .reg .u64 t; cvta.to.shared.u64 t, %1; cvt.u32.u64 %0, t; }" : "=r"(a) : "l"(p));
    return a;
}
__device__ __forceinline__ void ldsm4(uint32_t* r, uint32_t addr) {
    asm volatile("ldmatrix.sync.aligned.m8n8.x4.shared.b16 {%0,%1,%2,%3}, [%4];"
                 : "=r"(r[0]), "=r"(r[1]), "=r"(r[2]), "=r"(r[3]) : "r"(addr));
}
__device__ __forceinline__ void mma_f16(float* c, const uint32_t* a, const uint32_t* b) {
    asm volatile(
        "mma.sync.aligned.m16n8k16.row.col.f32.f16.f16.f32 "
        "{%0,%1,%2,%3}, {%4,%5,%6,%7}, {%8,%9}, {%0,%1,%2,%3};"
        : "+f"(c[0]), "+f"(c[1]), "+f"(c[2]), "+f"(c[3])
        : "r"(a[0]), "r"(a[1]), "r"(a[2]), "r"(a[3]), "r"(b[0]), "r"(b[1]));
}

// per-warp int64-vs-int32 edge dtype detection
__device__ __forceinline__ int detect_is64(const void* p) {
    int ok = 1;
    if ((threadIdx.x & 31) == 0) {
        const long long* q = (const long long*)p;
#pragma unroll
        for (int i = 0; i < 8; i++) {
            long long v = q[i];
            if (v < 0 || v >= (long long)N_MAX * 4) ok = 0;
        }
    }
    return __shfl_sync(0xffffffffu, ok, 0);
}

// ---------------- fused init: zero counters + pre-split both weights -------
__global__ void k_init(const float* __restrict__ W1, const float* __restrict__ W2, int n) {
    int i = blockIdx.x * blockDim.x + threadIdx.x;
    if (i < n) g_cnt[i] = 0;
    if (i < HID_DIM * IN_DIM) {
        int c = i >> 7, k = i & 127;
        float w = W1[(size_t)k * HID_DIM + c];
        __half h = __float2half_rn(w);
        __half l = __float2half_rn(w - __half2float(h));
        g_w1s[c * IN_DIM + k] = h;
        g_w1s[HID_DIM * IN_DIM + c * IN_DIM + k] = l;
    } else if (i < HID_DIM * IN_DIM + OUT_DIM * HID_DIM) {
        int j = i - HID_DIM * IN_DIM;
        int c = j >> 7, k = j & 127;
        float w = W2[(size_t)k * OUT_DIM + c];
        __half h = __float2half_rn(w);
        __half l = __float2half_rn(w - __half2float(h));
        g_w2s[c * HID_DIM + k] = h;
        g_w2s[OUT_DIM * HID_DIM + c * HID_DIM + k] = l;
    }
}

// ---------------- count (reads dst half of original edge buffer) -----------
__global__ void k_convcnt(const void* p, int E) {
    int is64 = detect_is64(p);
    int e = blockIdx.x * blockDim.x + threadIdx.x;
    if (e >= E) return;
    int d;
    if (is64) d = (int)((const long long*)p)[(size_t)E + e];
    else      d = ((const int*)p)[(size_t)E + e];
    atomicAdd(&g_cnt[d], 1);
}

// ---------------- scan / scatter ----------------
__global__ void k_scanA(int n) {
    __shared__ int sh[1024];
    int t = threadIdx.x;
    int idx = blockIdx.x * 1024 + t;
    int v = (idx < n) ? g_cnt[idx] : 0;
    sh[t] = v;
    __syncthreads();
#pragma unroll
    for (int off = 1; off < 1024; off <<= 1) {
        int add = (t >= off) ? sh[t - off] : 0;
        __syncthreads();
        sh[t] += add;
        __syncthreads();
    }
    int incl = sh[t];
    if (idx < n) g_rptr[idx] = incl - v;
    if (t == 1023) g_part[blockIdx.x] = incl;
}

__global__ void k_scanC(int n, int E) {
    __shared__ int bsum;
    int b = blockIdx.x;
    int npart = b >> 2;
    if (threadIdx.x < 32) {
        int acc = 0;
        for (int i = threadIdx.x; i < npart; i += 32) acc += g_part[i];
#pragma unroll
        for (int o = 16; o; o >>= 1) acc += __shfl_down_sync(0xffffffffu, acc, o);
        if (threadIdx.x == 0) bsum = acc;
    }
    __syncthreads();
    int idx = b * 256 + threadIdx.x;
    if (idx < n) {
        int r = g_rptr[idx] + bsum;
        g_rptr[idx] = r;
        g_cursor[idx] = r;
        g_dinv[idx] = rsqrtf((float)g_cnt[idx] + 1.0f);
    }
    if (idx == 0) g_rptr[n] = E;
}

__global__ void k_scatter(const void* p, int E) {
    int is64 = detect_is64(p);
    int e = blockIdx.x * blockDim.x + threadIdx.x;
    if (e >= E) return;
    int s, d;
    if (is64) {
        const long long* q = (const long long*)p;
        s = (int)q[e];
        d = (int)q[(size_t)E + e];
    } else {
        const int* q = (const int*)p;
        s = q[e];
        d = q[(size_t)E + e];
    }
    int pos = atomicAdd(&g_cursor[d], 1);
    g_csr[pos] = s;
}

// ---------------- GEMM: G(fp16) = A @ W, BM=128, fp16 2-product ------------
// Persistent CTAs. Warp grid 2(m)x4(n): warp tile 64 rows x NC/4 cols.
// Per warp-k-step: A 4 LDSM + B (NF/2)*2 LDSM feeding 4*NF*2 MMAs.
template <int NC, typename TIn>
__global__ __launch_bounds__(256, 2) void k_gemm(
    const TIn* __restrict__ X, const __half* __restrict__ Ws,
    __half* __restrict__ G, int n, int ntiles)
{
    extern __shared__ char smem[];
    constexpr int PITCH = 272;
    constexpr int BM = 128;
    constexpr int AH = 0;
    constexpr int BH = AH + BM * PITCH;
    constexpr int BL = BH + NC * PITCH;
    constexpr int NF = NC / 32;             // 4 (NC=128) or 2 (NC=64)

    uint32_t sb = smem_u32(smem);
    int tid = threadIdx.x;

    // ---- B once per CTA: W hi/lo fp16 (NC x 128 each) ----
    {
        constexpr int BU4 = NC * 128 * 2 / 16;
        const uint4* ws4 = (const uint4*)Ws;
#pragma unroll
        for (int r = 0; r < BU4 / 256; r++) {
            int li = tid + r * 256;
            int c = li >> 4;
            int ch = li & 15;
            *(uint4*)(smem + BH + c * PITCH + ch * 16) = ws4[li];
            *(uint4*)(smem + BL + c * PITCH + ch * 16) = ws4[BU4 + li];
        }
    }

    int wid = tid >> 5;
    int lane = tid & 31;
    int wm = wid & 1;
    int wn = wid >> 1;
    int m0 = wm * 64;                       // 64-row warp tile
    int n0 = wn * (NC / 4);

    uint32_t a_addr0 = sb + AH + (uint32_t)(m0 + (lane & 15)) * PITCH + ((lane >> 4) * 16);
    uint32_t b_row   = (uint32_t)(n0 + (lane & 7) + ((lane >> 4) & 1) * 8);
    uint32_t b_addr0 = sb + BH + b_row * PITCH + (((lane >> 3) & 1) * 16);

    for (int tile = blockIdx.x; tile < ntiles; tile += gridDim.x) {
        int mbase = tile * BM;

        // ---- A prologue ----
        if constexpr (sizeof(TIn) == 4) {
            // fp32 -> fp16 quantize: row = tid>>1, 64 k values
            int ar = tid >> 1;
            int ak0 = (tid & 1) * 64;
            int row = mbase + ar;
            char* ap = smem + AH + ar * PITCH;
#pragma unroll
            for (int k = ak0; k < ak0 + 64; k += 4) {
                float4 v = make_float4(0.f, 0.f, 0.f, 0.f);
                if (row < n) v = *(const float4*)((const float*)X + (size_t)row * IN_DIM + k);
                __half2 p0 = __floats2half2_rn(v.x, v.y);
                __half2 p1 = __floats2half2_rn(v.z, v.w);
                uint2 u; u.x = *(uint32_t*)&p0; u.y = *(uint32_t*)&p1;
                *(uint2*)(ap + k * 2) = u;
            }
        } else {
            // raw fp16 copy: 128 rows x 256B = 2048 uint4
#pragma unroll
            for (int r = 0; r < 8; r++) {
                int li = tid + r * 256;
                int row = li >> 4;
                int ch = li & 15;
                uint4 v = make_uint4(0, 0, 0, 0);
                if (mbase + row < n)
                    v = *(const uint4*)((const char*)((const __half*)X + (size_t)(mbase + row) * IN_DIM) + ch * 16);
                *(uint4*)(smem + AH + row * PITCH + ch * 16) = v;
            }
        }
        __syncthreads();

        float acc[4][NF][4];
#pragma unroll
        for (int mi = 0; mi < 4; mi++)
#pragma unroll
            for (int nf = 0; nf < NF; nf++)
#pragma unroll
                for (int q = 0; q < 4; q++) acc[mi][nf][q] = 0.0f;

#pragma unroll
        for (int ks = 0; ks < 8; ks++) {
            uint32_t koff = ks * 32;
            uint32_t a[4][4];
#pragma unroll
            for (int mi = 0; mi < 4; mi++)
                ldsm4(a[mi], a_addr0 + mi * 16 * PITCH + koff);
            uint32_t bh[NF][2], bl[NF][2];
#pragma unroll
            for (int pr = 0; pr < NF / 2; pr++) {
                uint32_t r[4];
                ldsm4(r, b_addr0 + pr * 16 * PITCH + koff);
                bh[2 * pr][0] = r[0]; bh[2 * pr][1] = r[1];
                bh[2 * pr + 1][0] = r[2]; bh[2 * pr + 1][1] = r[3];
                ldsm4(r, b_addr0 + (BL - BH) + pr * 16 * PITCH + koff);
                bl[2 * pr][0] = r[0]; bl[2 * pr][1] = r[1];
                bl[2 * pr + 1][0] = r[2]; bl[2 * pr + 1][1] = r[3];
            }
#pragma unroll
            for (int mi = 0; mi < 4; mi++)
#pragma unroll
                for (int nf = 0; nf < NF; nf++) {
                    mma_f16(acc[mi][nf], a[mi], bh[nf]);
                    mma_f16(acc[mi][nf], a[mi], bl[nf]);
                }
        }

        // ---- epilogue: fp16 stores ----
#pragma unroll
        for (int mi = 0; mi < 4; mi++) {
            int r0 = mbase + m0 + mi * 16 + (lane >> 2);
#pragma unroll
            for (int nf = 0; nf < NF; nf++) {
                int col = n0 + nf * 8 + 2 * (lane & 3);
                if (r0 < n) {
                    __half2 v = __floats2half2_rn(acc[mi][nf][0], acc[mi][nf][1]);
                    *(__half2*)(G + (size_t)r0 * NC + col) = v;
                }
                if (r0 + 8 < n) {
                    __half2 v = __floats2half2_rn(acc[mi][nf][2], acc[mi][nf][3]);
                    *(__half2*)(G + (size_t)(r0 + 8) * NC + col) = v;
                }
            }
        }
        __syncthreads();
    }
}

// -------- aggregation: OUT[i] = act(dinv[i]*(sum_j dinv[j]*G[j] + dinv[i]*G[i]) + bias)
template <int NC, bool RELU, typename OutT>
__global__ __launch_bounds__(256) void k_agg(
    const __half* __restrict__ G, const float* __restrict__ bias,
    OutT* __restrict__ OUT, int n)
{
    constexpr int V = NC / 32;
    constexpr int V2 = V / 2;
    int gw = (blockIdx.x * blockDim.x + threadIdx.x) >> 5;
    int lane = threadIdx.x & 31;
    if (gw >= n) return;

    float di = g_dinv[gw];

    float acc[V];
    {
        const __half2* ps = (const __half2*)(G + (size_t)gw * NC + lane * V);
#pragma unroll
        for (int q = 0; q < V2; q++) {
            float2 fv = __half22float2(ps[q]);
            acc[2 * q] = di * fv.x;
            acc[2 * q + 1] = di * fv.y;
        }
    }

    int s = g_rptr[gw], e = g_rptr[gw + 1];
    for (int base = s; base < e; base += 32) {
        int idx = base + lane;
        int sj = 0;
        float dj = 0.0f;
        if (idx < e) {
            sj = g_csr[idx];
            dj = g_dinv[sj];
        }
        int m = e - base; if (m > 32) m = 32;
        int j = 0;
        for (; j + 4 <= m; j += 4) {
            int s0 = __shfl_sync(0xffffffffu, sj, j);
            int s1 = __shfl_sync(0xffffffffu, sj, j + 1);
            int s2 = __shfl_sync(0xffffffffu, sj, j + 2);
            int s3 = __shfl_sync(0xffffffffu, sj, j + 3);
            float d0 = __shfl_sync(0xffffffffu, dj, j);
            float d1 = __shfl_sync(0xffffffffu, dj, j + 1);
            float d2 = __shfl_sync(0xffffffffu, dj, j + 2);
            float d3 = __shfl_sync(0xffffffffu, dj, j + 3);
            const __half2* p0 = (const __half2*)(G + (size_t)s0 * NC + lane * V);
            const __half2* p1 = (const __half2*)(G + (size_t)s1 * NC + lane * V);
            const __half2* p2 = (const __half2*)(G + (size_t)s2 * NC + lane * V);
            const __half2* p3 = (const __half2*)(G + (size_t)s3 * NC + lane * V);
#pragma unroll
            for (int q = 0; q < V2; q++) {
                float2 a = __half22float2(p0[q]);
                float2 b = __half22float2(p1[q]);
                float2 c = __half22float2(p2[q]);
                float2 d = __half22float2(p3[q]);
                acc[2 * q]     += d0 * a.x + d1 * b.x + d2 * c.x + d3 * d.x;
                acc[2 * q + 1] += d0 * a.y + d1 * b.y + d2 * c.y + d3 * d.y;
            }
        }
        for (; j < m; j++) {
            int s0 = __shfl_sync(0xffffffffu, sj, j);
            float d0 = __shfl_sync(0xffffffffu, dj, j);
            const __half2* p = (const __half2*)(G + (size_t)s0 * NC + lane * V);
#pragma unroll
            for (int q = 0; q < V2; q++) {
                float2 a = __half22float2(p[q]);
                acc[2 * q]     += d0 * a.x;
                acc[2 * q + 1] += d0 * a.y;
            }
        }
    }

    float bv[V];
#pragma unroll
    for (int q = 0; q < V2; q++) {
        float2 b = *(const float2*)(bias + lane * V + 2 * q);
        bv[2 * q] = b.x; bv[2 * q + 1] = b.y;
    }
    float r[V];
#pragma unroll
    for (int v = 0; v < V; v++) {
        r[v] = acc[v] * di + bv[v];
        if (RELU) r[v] = fmaxf(r[v], 0.0f);
    }
    if constexpr (sizeof(OutT) == 2) {
        __half2* po = (__half2*)((__half*)OUT + (size_t)gw * NC + lane * V);
#pragma unroll
        for (int q = 0; q < V2; q++)
            po[q] = __floats2half2_rn(r[2 * q], r[2 * q + 1]);
    } else {
        float* po = (float*)OUT + (size_t)gw * NC + lane * V;
#pragma unroll
        for (int q = 0; q < V2; q++) {
            float2 o; o.x = r[2 * q]; o.y = r[2 * q + 1];
            *(float2*)(po + 2 * q) = o;
        }
    }
}

// ---------------- launch ----------------
extern "C" void kernel_launch(void* const* d_in, const int* in_sizes, int n_in,
                              void* d_out, int out_size)
{
    const float* x  = (const float*)d_in[0];
    const void*  ei = d_in[1];
    const float* W1 = (const float*)d_in[2];
    const float* b1 = (const float*)d_in[3];
    const float* W2 = (const float*)d_in[4];
    const float* b2 = (const float*)d_in[5];
    float* out = (float*)d_out;

    int n = in_sizes[0] / IN_DIM;
    int E = in_sizes[1] / 2;

    __half *g1p, *h1p, *g2p, *w1s, *w2s;
    cudaGetSymbolAddress((void**)&g1p, g_g1);
    cudaGetSymbolAddress((void**)&h1p, g_h1);
    cudaGetSymbolAddress((void**)&g2p, g_g2);
    cudaGetSymbolAddress((void**)&w1s, g_w1s);
    cudaGetSymbolAddress((void**)&w2s, g_w2s);

    const int smem1 = 128 * 272 + 2 * 128 * 272;   // 104448 -> 2 CTAs/SM
    const int smem2 = 128 * 272 + 2 * 64 * 272;    //  69632 -> 2 CTAs/SM (regs)
    cudaFuncSetAttribute((const void*)k_gemm<HID_DIM, float>,
                         cudaFuncAttributeMaxDynamicSharedMemorySize, smem1);
    cudaFuncSetAttribute((const void*)k_gemm<OUT_DIM, __half>,
                         cudaFuncAttributeMaxDynamicSharedMemorySize, smem2);

    int nb1024 = (n + 1023) / 1024;
    int ntiles = (n + 127) / 128;
    int pg = (ntiles < 296) ? ntiles : 296;
    int igrid = (n > HID_DIM * IN_DIM + OUT_DIM * HID_DIM ? n
                 : HID_DIM * IN_DIM + OUT_DIM * HID_DIM);

    k_init<<<(igrid + 255) / 256, 256>>>(W1, W2, n);                        // 0
    k_convcnt<<<(E + 255) / 256, 256>>>(ei, E);                             // 1
    k_scanA<<<nb1024, 1024>>>(n);                                           // 2
    k_gemm<HID_DIM, float><<<pg, 256, smem1>>>(x, w1s, g1p, n, ntiles);     // 3 (ncu slot)
    k_scanC<<<(n + 255) / 256, 256>>>(n, E);                                // 4
    k_scatter<<<(E + 255) / 256, 256>>>(ei, E);                             // 5
    k_agg<HID_DIM, true, __half><<<(n * 32 + 255) / 256, 256>>>(g1p, b1, h1p, n);   // 6
    k_gemm<OUT_DIM, __half><<<pg, 256, smem2>>>(h1p, w2s, g2p, n, ntiles);  // 7
    k_agg<OUT_DIM, false, float><<<(n * 32 + 255) / 256, 256>>>(g2p, b2, out, n);   // 8
}

// round 14
// speedup vs baseline: 1.0733x; 1.0733x over previous
#include <cuda_runtime.h>
#include <cuda_bf16.h>
#include <cuda_fp16.h>
#include <cstdint>

// ---------------- problem constants ----------------
#define N_MAX 100000
#define E_MAX 1600000
#define IN_DIM 128
#define HID_DIM 128
#define OUT_DIM 64

typedef unsigned long long u64;

// ---------------- device scratch ----------------
__device__ int   g_cnt[N_MAX];
__device__ int   g_rptr[N_MAX + 1];
__device__ int   g_cursor[N_MAX];
__device__ int   g_part[256];
__device__ float g_dinv[N_MAX];
__device__ int   g_csr[E_MAX];
// fp16 message/feature buffers
__device__ __align__(16) __half g_g1[(size_t)N_MAX * HID_DIM];
__device__ __align__(16) __half g_h1[(size_t)N_MAX * HID_DIM];
__device__ __align__(16) __half g_g2[(size_t)N_MAX * OUT_DIM];
// W1 and W2 pre-split fp16 hi/lo, layout Wt[c][k] (k contiguous), hi block then lo
__device__ __align__(16) __half g_w1s[2 * HID_DIM * IN_DIM];
__device__ __align__(16) __half g_w2s[2 * OUT_DIM * HID_DIM];

// ---------------- PTX helpers (baseline ISA: ldmatrix + mma.sync) ----------
__device__ __forceinline__ uint32_t smem_u32(const void* p) {
    uint32_t a;
    asm("{ .reg .u64 t; cvta.to.shared.u64 t, %1; cvt.u32.u64 %0, t; }" : "=r"(a) : "l"(p));
    return a;
}
__device__ __forceinline__ void ldsm4(uint32_t* r, uint32_t addr) {
    asm volatile("ldmatrix.sync.aligned.m8n8.x4.shared.b16 {%0,%1,%2,%3}, [%4];"
                 : "=r"(r[0]), "=r"(r[1]), "=r"(r[2]), "=r"(r[3]) : "r"(addr));
}
__device__ __forceinline__ void mma_f16(float* c, const uint32_t* a, const uint32_t* b) {
    asm volatile(
        "mma.sync.aligned.m16n8k16.row.col.f32.f16.f16.f32 "
        "{%0,%1,%2,%3}, {%4,%5,%6,%7}, {%8,%9}, {%0,%1,%2,%3};"
        : "+f"(c[0]), "+f"(c[1]), "+f"(c[2]), "+f"(c[3])
        : "r"(a[0]), "r"(a[1]), "r"(a[2]), "r"(a[3]), "r"(b[0]), "r"(b[1]));
}

// per-warp int64-vs-int32 edge dtype detection
__device__ __forceinline__ int detect_is64(const void* p) {
    int ok = 1;
    if ((threadIdx.x & 31) == 0) {
        const long long* q = (const long long*)p;
#pragma unroll
        for (int i = 0; i < 8; i++) {
            long long v = q[i];
            if (v < 0 || v >= (long long)N_MAX * 4) ok = 0;
        }
    }
    return __shfl_sync(0xffffffffu, ok, 0);
}

// ---------------- fused init: zero counters + pre-split both weights -------
__global__ void k_init(const float* __restrict__ W1, const float* __restrict__ W2, int n) {
    int i = blockIdx.x * blockDim.x + threadIdx.x;
    if (i < n) g_cnt[i] = 0;
    if (i < HID_DIM * IN_DIM) {
        int c = i >> 7, k = i & 127;
        float w = W1[(size_t)k * HID_DIM + c];
        __half h = __float2half_rn(w);
        __half l = __float2half_rn(w - __half2float(h));
        g_w1s[c * IN_DIM + k] = h;
        g_w1s[HID_DIM * IN_DIM + c * IN_DIM + k] = l;
    } else if (i < HID_DIM * IN_DIM + OUT_DIM * HID_DIM) {
        int j = i - HID_DIM * IN_DIM;
        int c = j >> 7, k = j & 127;
        float w = W2[(size_t)k * OUT_DIM + c];
        __half h = __float2half_rn(w);
        __half l = __float2half_rn(w - __half2float(h));
        g_w2s[c * HID_DIM + k] = h;
        g_w2s[OUT_DIM * HID_DIM + c * HID_DIM + k] = l;
    }
}

// ---------------- count (reads dst half of original edge buffer) -----------
__global__ void k_convcnt(const void* p, int E) {
    int is64 = detect_is64(p);
    int e = blockIdx.x * blockDim.x + threadIdx.x;
    if (e >= E) return;
    int d;
    if (is64) d = (int)((const long long*)p)[(size_t)E + e];
    else      d = ((const int*)p)[(size_t)E + e];
    atomicAdd(&g_cnt[d], 1);
}

// ---------------- scan / scatter ----------------
__global__ void k_scanA(int n) {
    __shared__ int sh[1024];
    int t = threadIdx.x;
    int idx = blockIdx.x * 1024 + t;
    int v = (idx < n) ? g_cnt[idx] : 0;
    sh[t] = v;
    __syncthreads();
#pragma unroll
    for (int off = 1; off < 1024; off <<= 1) {
        int add = (t >= off) ? sh[t - off] : 0;
        __syncthreads();
        sh[t] += add;
        __syncthreads();
    }
    int incl = sh[t];
    if (idx < n) g_rptr[idx] = incl - v;
    if (t == 1023) g_part[blockIdx.x] = incl;
}

__global__ void k_scanC(int n, int E) {
    __shared__ int bsum;
    int b = blockIdx.x;
    int npart = b >> 2;
    if (threadIdx.x < 32) {
        int acc = 0;
        for (int i = threadIdx.x; i < npart; i += 32) acc += g_part[i];
#pragma unroll
        for (int o = 16; o; o >>= 1) acc += __shfl_down_sync(0xffffffffu, acc, o);
        if (threadIdx.x == 0) bsum = acc;
    }
    __syncthreads();
    int idx = b * 256 + threadIdx.x;
    if (idx < n) {
        int r = g_rptr[idx] + bsum;
        g_rptr[idx] = r;
        g_cursor[idx] = r;
        g_dinv[idx] = rsqrtf((float)g_cnt[idx] + 1.0f);
    }
    if (idx == 0) g_rptr[n] = E;
}

__global__ void k_scatter(const void* p, int E) {
    int is64 = detect_is64(p);
    int e = blockIdx.x * blockDim.x + threadIdx.x;
    if (e >= E) return;
    int s, d;
    if (is64) {
        const long long* q = (const long long*)p;
        s = (int)q[e];
        d = (int)q[(size_t)E + e];
    } else {
        const int* q = (const int*)p;
        s = q[e];
        d = q[(size_t)E + e];
    }
    int pos = atomicAdd(&g_cursor[d], 1);
    g_csr[pos] = s;
}

// ---------------- GEMM: G(fp16) = A @ W, BM=64, fp16 2-product -------------
// (round-12 known-good config)
template <int NC, typename TIn>
__global__ __launch_bounds__(256, 2) void k_gemm(
    const TIn* __restrict__ X, const __half* __restrict__ Ws,
    __half* __restrict__ G, int n, int ntiles)
{
    extern __shared__ char smem[];
    constexpr int PITCH = 272;
    constexpr int BM = 64;
    constexpr int AH = 0;
    constexpr int BH = AH + BM * PITCH;
    constexpr int BL = BH + NC * PITCH;
    constexpr int NF = NC / 32;

    uint32_t sb = smem_u32(smem);
    int tid = threadIdx.x;

    // ---- B once per CTA: W hi/lo fp16 (NC x 128 each) ----
    {
        constexpr int BU4 = NC * 128 * 2 / 16;
        const uint4* ws4 = (const uint4*)Ws;
#pragma unroll
        for (int r = 0; r < BU4 / 256; r++) {
            int li = tid + r * 256;
            int c = li >> 4;
            int ch = li & 15;
            *(uint4*)(smem + BH + c * PITCH + ch * 16) = ws4[li];
            *(uint4*)(smem + BL + c * PITCH + ch * 16) = ws4[BU4 + li];
        }
    }

    int wid = tid >> 5;
    int lane = tid & 31;
    int wm = wid & 1;
    int wn = wid >> 1;
    int m0 = wm * 32;
    int n0 = wn * (NC / 4);

    uint32_t a_addr0 = sb + AH + (uint32_t)(m0 + (lane & 15)) * PITCH + ((lane >> 4) * 16);
    uint32_t b_row   = (uint32_t)(n0 + (lane & 7) + ((lane >> 4) & 1) * 8);
    uint32_t b_addr0 = sb + BH + b_row * PITCH + (((lane >> 3) & 1) * 16);

    for (int tile = blockIdx.x; tile < ntiles; tile += gridDim.x) {
        int mbase = tile * BM;

        // ---- A prologue ----
        if constexpr (sizeof(TIn) == 4) {
            int ar = tid >> 2;
            int ak0 = (tid & 3) * 32;
            int row = mbase + ar;
            char* ap = smem + AH + ar * PITCH;
#pragma unroll
            for (int k = ak0; k < ak0 + 32; k += 4) {
                float4 v = make_float4(0.f, 0.f, 0.f, 0.f);
                if (row < n) v = *(const float4*)((const float*)X + (size_t)row * IN_DIM + k);
                __half2 p0 = __floats2half2_rn(v.x, v.y);
                __half2 p1 = __floats2half2_rn(v.z, v.w);
                uint2 u; u.x = *(uint32_t*)&p0; u.y = *(uint32_t*)&p1;
                *(uint2*)(ap + k * 2) = u;
            }
        } else {
#pragma unroll
            for (int r = 0; r < 4; r++) {
                int li = tid + r * 256;
                int row = li >> 4;
                int ch = li & 15;
                uint4 v = make_uint4(0, 0, 0, 0);
                if (mbase + row < n)
                    v = *(const uint4*)((const char*)((const __half*)X + (size_t)(mbase + row) * IN_DIM) + ch * 16);
                *(uint4*)(smem + AH + row * PITCH + ch * 16) = v;
            }
        }
        __syncthreads();

        float acc[2][NF][4];
#pragma unroll
        for (int mi = 0; mi < 2; mi++)
#pragma unroll
            for (int nf = 0; nf < NF; nf++)
#pragma unroll
                for (int q = 0; q < 4; q++) acc[mi][nf][q] = 0.0f;

#pragma unroll
        for (int ks = 0; ks < 8; ks++) {
            uint32_t koff = ks * 32;
            uint32_t a[2][4];
            ldsm4(a[0], a_addr0 + koff);
            ldsm4(a[1], a_addr0 + 16 * PITCH + koff);
            uint32_t bh[NF][2], bl[NF][2];
#pragma unroll
            for (int pr = 0; pr < NF / 2; pr++) {
                uint32_t r[4];
                ldsm4(r, b_addr0 + pr * 16 * PITCH + koff);
                bh[2 * pr][0] = r[0]; bh[2 * pr][1] = r[1];
                bh[2 * pr + 1][0] = r[2]; bh[2 * pr + 1][1] = r[3];
                ldsm4(r, b_addr0 + (BL - BH) + pr * 16 * PITCH + koff);
                bl[2 * pr][0] = r[0]; bl[2 * pr][1] = r[1];
                bl[2 * pr + 1][0] = r[2]; bl[2 * pr + 1][1] = r[3];
            }
#pragma unroll
            for (int mi = 0; mi < 2; mi++)
#pragma unroll
                for (int nf = 0; nf < NF; nf++) {
                    mma_f16(acc[mi][nf], a[mi], bh[nf]);
                    mma_f16(acc[mi][nf], a[mi], bl[nf]);
                }
        }

        // ---- epilogue: fp16 stores ----
#pragma unroll
        for (int mi = 0; mi < 2; mi++) {
            int r0 = mbase + m0 + mi * 16 + (lane >> 2);
#pragma unroll
            for (int nf = 0; nf < NF; nf++) {
                int col = n0 + nf * 8 + 2 * (lane & 3);
                if (r0 < n) {
                    __half2 v = __floats2half2_rn(acc[mi][nf][0], acc[mi][nf][1]);
                    *(__half2*)(G + (size_t)r0 * NC + col) = v;
                }
                if (r0 + 8 < n) {
                    __half2 v = __floats2half2_rn(acc[mi][nf][2], acc[mi][nf][3]);
                    *(__half2*)(G + (size_t)(r0 + 8) * NC + col) = v;
                }
            }
        }
        __syncthreads();
    }
}

// -------- aggregation: OUT[i] = act(dinv[i]*(sum_j dinv[j]*G[j] + dinv[i]*G[i]) + bias)
template <int NC, bool RELU, typename OutT>
__global__ __launch_bounds__(256) void k_agg(
    const __half* __restrict__ G, const float* __restrict__ bias,
    OutT* __restrict__ OUT, int n)
{
    constexpr int V = NC / 32;
    constexpr int V2 = V / 2;
    int gw = (blockIdx.x * blockDim.x + threadIdx.x) >> 5;
    int lane = threadIdx.x & 31;
    if (gw >= n) return;

    float di = g_dinv[gw];

    float acc[V];
    {
        const __half2* ps = (const __half2*)(G + (size_t)gw * NC + lane * V);
#pragma unroll
        for (int q = 0; q < V2; q++) {
            float2 fv = __half22float2(ps[q]);
            acc[2 * q] = di * fv.x;
            acc[2 * q + 1] = di * fv.y;
        }
    }

    int s = g_rptr[gw], e = g_rptr[gw + 1];
    for (int base = s; base < e; base += 32) {
        int idx = base + lane;
        int sj = 0;
        float dj = 0.0f;
        if (idx < e) {
            sj = g_csr[idx];
            dj = g_dinv[sj];
        }
        int m = e - base; if (m > 32) m = 32;
        int j = 0;
        for (; j + 4 <= m; j += 4) {
            int s0 = __shfl_sync(0xffffffffu, sj, j);
            int s1 = __shfl_sync(0xffffffffu, sj, j + 1);
            int s2 = __shfl_sync(0xffffffffu, sj, j + 2);
            int s3 = __shfl_sync(0xffffffffu, sj, j + 3);
            float d0 = __shfl_sync(0xffffffffu, dj, j);
            float d1 = __shfl_sync(0xffffffffu, dj, j + 1);
            float d2 = __shfl_sync(0xffffffffu, dj, j + 2);
            float d3 = __shfl_sync(0xffffffffu, dj, j + 3);
            const __half2* p0 = (const __half2*)(G + (size_t)s0 * NC + lane * V);
            const __half2* p1 = (const __half2*)(G + (size_t)s1 * NC + lane * V);
            const __half2* p2 = (const __half2*)(G + (size_t)s2 * NC + lane * V);
            const __half2* p3 = (const __half2*)(G + (size_t)s3 * NC + lane * V);
#pragma unroll
            for (int q = 0; q < V2; q++) {
                float2 a = __half22float2(p0[q]);
                float2 b = __half22float2(p1[q]);
                float2 c = __half22float2(p2[q]);
                float2 d = __half22float2(p3[q]);
                acc[2 * q]     += d0 * a.x + d1 * b.x + d2 * c.x + d3 * d.x;
                acc[2 * q + 1] += d0 * a.y + d1 * b.y + d2 * c.y + d3 * d.y;
            }
        }
        for (; j < m; j++) {
            int s0 = __shfl_sync(0xffffffffu, sj, j);
            float d0 = __shfl_sync(0xffffffffu, dj, j);
            const __half2* p = (const __half2*)(G + (size_t)s0 * NC + lane * V);
#pragma unroll
            for (int q = 0; q < V2; q++) {
                float2 a = __half22float2(p[q]);
                acc[2 * q]     += d0 * a.x;
                acc[2 * q + 1] += d0 * a.y;
            }
        }
    }

    float bv[V];
#pragma unroll
    for (int q = 0; q < V2; q++) {
        float2 b = *(const float2*)(bias + lane * V + 2 * q);
        bv[2 * q] = b.x; bv[2 * q + 1] = b.y;
    }
    float r[V];
#pragma unroll
    for (int v = 0; v < V; v++) {
        r[v] = acc[v] * di + bv[v];
        if (RELU) r[v] = fmaxf(r[v], 0.0f);
    }
    if constexpr (sizeof(OutT) == 2) {
        __half2* po = (__half2*)((__half*)OUT + (size_t)gw * NC + lane * V);
#pragma unroll
        for (int q = 0; q < V2; q++)
            po[q] = __floats2half2_rn(r[2 * q], r[2 * q + 1]);
    } else {
        float* po = (float*)OUT + (size_t)gw * NC + lane * V;
#pragma unroll
        for (int q = 0; q < V2; q++) {
            float2 o; o.x = r[2 * q]; o.y = r[2 * q + 1];
            *(float2*)(po + 2 * q) = o;
        }
    }
}

// ---------------- launch ----------------
extern "C" void kernel_launch(void* const* d_in, const int* in_sizes, int n_in,
                              void* d_out, int out_size)
{
    const float* x  = (const float*)d_in[0];
    const void*  ei = d_in[1];
    const float* W1 = (const float*)d_in[2];
    const float* b1 = (const float*)d_in[3];
    const float* W2 = (const float*)d_in[4];
    const float* b2 = (const float*)d_in[5];
    float* out = (float*)d_out;

    int n = in_sizes[0] / IN_DIM;
    int E = in_sizes[1] / 2;

    __half *g1p, *h1p, *g2p, *w1s, *w2s;
    cudaGetSymbolAddress((void**)&g1p, g_g1);
    cudaGetSymbolAddress((void**)&h1p, g_h1);
    cudaGetSymbolAddress((void**)&g2p, g_g2);
    cudaGetSymbolAddress((void**)&w1s, g_w1s);
    cudaGetSymbolAddress((void**)&w2s, g_w2s);

    const int smem1 = 64 * 272 + 2 * 128 * 272;   // 87040 -> 2 CTAs/SM
    const int smem2 = 64 * 272 + 2 * 64 * 272;    // 52224 -> 4 CTAs/SM
    cudaFuncSetAttribute((const void*)k_gemm<HID_DIM, float>,
                         cudaFuncAttributeMaxDynamicSharedMemorySize, smem1);
    cudaFuncSetAttribute((const void*)k_gemm<OUT_DIM, __half>,
                         cudaFuncAttributeMaxDynamicSharedMemorySize, smem2);

    // side stream + fork/join events (host objects, created once)
    static cudaStream_t s2 = nullptr;
    static cudaEvent_t evFork = nullptr, evJoin = nullptr;
    if (!s2) {
        cudaStreamCreateWithFlags(&s2, cudaStreamNonBlocking);
        cudaEventCreateWithFlags(&evFork, cudaEventDisableTiming);
        cudaEventCreateWithFlags(&evJoin, cudaEventDisableTiming);
    }

    int nb1024 = (n + 1023) / 1024;
    int ntiles = (n + 63) / 64;
    int pg1 = (ntiles < 296) ? ntiles : 296;
    int pg2 = (ntiles < 592) ? ntiles : 592;
    int igrid = (n > HID_DIM * IN_DIM + OUT_DIM * HID_DIM ? n
                 : HID_DIM * IN_DIM + OUT_DIM * HID_DIM);

    // main stream: init (zeroes g_cnt + splits weights)
    k_init<<<(igrid + 255) / 256, 256>>>(W1, W2, n);

    // fork: CSR chain on s2, concurrent with gemm1 on main stream
    cudaEventRecord(evFork, 0);
    cudaStreamWaitEvent(s2, evFork, 0);

    k_convcnt<<<(E + 255) / 256, 256, 0, s2>>>(ei, E);
    k_scanA<<<nb1024, 1024, 0, s2>>>(n);
    k_scanC<<<(n + 255) / 256, 256, 0, s2>>>(n, E);
    k_scatter<<<(E + 255) / 256, 256, 0, s2>>>(ei, E);
    cudaEventRecord(evJoin, s2);

    k_gemm<HID_DIM, float><<<pg1, 256, smem1>>>(x, w1s, g1p, n, ntiles);

    // join: agg1 needs both gemm1 (stream order) and CSR (event)
    cudaStreamWaitEvent(0, evJoin, 0);

    k_agg<HID_DIM, true, __half><<<(n * 32 + 255) / 256, 256>>>(g1p, b1, h1p, n);
    k_gemm<OUT_DIM, __half><<<pg2, 256, smem2>>>(h1p, w2s, g2p, n, ntiles);
    k_agg<OUT_DIM, false, float><<<(n * 32 + 255) / 256, 256>>>(g2p, b2, out, n);
}

// round 15
// speedup vs baseline: 1.1690x; 1.0892x over previous
#include <cuda_runtime.h>
#include <cuda_bf16.h>
#include <cuda_fp16.h>
#include <cstdint>

// ---------------- problem constants ----------------
#define N_MAX 100000
#define E_MAX 1600000
#define IN_DIM 128
#define HID_DIM 128
#define OUT_DIM 64

typedef unsigned long long u64;

// ---------------- device scratch ----------------
__device__ int   g_cnt[N_MAX];
__device__ int   g_rptr[N_MAX + 1];
__device__ int   g_cursor[N_MAX];
__device__ int   g_part[256];
__device__ int   g_csr[E_MAX];
// fp16 message/feature buffers (rows pre-scaled by dinv[src])
__device__ __align__(16) __half g_g1[(size_t)N_MAX * HID_DIM];
__device__ __align__(16) __half g_h1[(size_t)N_MAX * HID_DIM];   // dinv * relu(...)
__device__ __align__(16) __half g_g2[(size_t)N_MAX * OUT_DIM];
// W1 and W2 pre-split fp16 hi/lo, layout Wt[c][k] (k contiguous), hi block then lo
__device__ __align__(16) __half g_w1s[2 * HID_DIM * IN_DIM];
__device__ __align__(16) __half g_w2s[2 * OUT_DIM * HID_DIM];

// ---------------- PTX helpers (baseline ISA: ldmatrix + mma.sync) ----------
__device__ __forceinline__ uint32_t smem_u32(const void* p) {
    uint32_t a;
    asm("{ .reg .u64 t; cvta.to.shared.u64 t, %1; cvt.u32.u64 %0, t; }" : "=r"(a) : "l"(p));
    return a;
}
__device__ __forceinline__ void ldsm4(uint32_t* r, uint32_t addr) {
    asm volatile("ldmatrix.sync.aligned.m8n8.x4.shared.b16 {%0,%1,%2,%3}, [%4];"
                 : "=r"(r[0]), "=r"(r[1]), "=r"(r[2]), "=r"(r[3]) : "r"(addr));
}
__device__ __forceinline__ void mma_f16(float* c, const uint32_t* a, const uint32_t* b) {
    asm volatile(
        "mma.sync.aligned.m16n8k16.row.col.f32.f16.f16.f32 "
        "{%0,%1,%2,%3}, {%4,%5,%6,%7}, {%8,%9}, {%0,%1,%2,%3};"
        : "+f"(c[0]), "+f"(c[1]), "+f"(c[2]), "+f"(c[3])
        : "r"(a[0]), "r"(a[1]), "r"(a[2]), "r"(a[3]), "r"(b[0]), "r"(b[1]));
}

// per-warp int64-vs-int32 edge dtype detection
__device__ __forceinline__ int detect_is64(const void* p) {
    int ok = 1;
    if ((threadIdx.x & 31) == 0) {
        const long long* q = (const long long*)p;
#pragma unroll
        for (int i = 0; i < 8; i++) {
            long long v = q[i];
            if (v < 0 || v >= (long long)N_MAX * 4) ok = 0;
        }
    }
    return __shfl_sync(0xffffffffu, ok, 0);
}

// ---------------- fused init: zero counters + pre-split both weights -------
__global__ void k_init(const float* __restrict__ W1, const float* __restrict__ W2, int n) {
    int i = blockIdx.x * blockDim.x + threadIdx.x;
    if (i < n) g_cnt[i] = 0;
    if (i < HID_DIM * IN_DIM) {
        int c = i >> 7, k = i & 127;
        float w = W1[(size_t)k * HID_DIM + c];
        __half h = __float2half_rn(w);
        __half l = __float2half_rn(w - __half2float(h));
        g_w1s[c * IN_DIM + k] = h;
        g_w1s[HID_DIM * IN_DIM + c * IN_DIM + k] = l;
    } else if (i < HID_DIM * IN_DIM + OUT_DIM * HID_DIM) {
        int j = i - HID_DIM * IN_DIM;
        int c = j >> 7, k = j & 127;
        float w = W2[(size_t)k * OUT_DIM + c];
        __half h = __float2half_rn(w);
        __half l = __float2half_rn(w - __half2float(h));
        g_w2s[c * HID_DIM + k] = h;
        g_w2s[OUT_DIM * HID_DIM + c * HID_DIM + k] = l;
    }
}

// ---------------- count (reads dst half of original edge buffer) -----------
__global__ void k_convcnt(const void* p, int E) {
    int is64 = detect_is64(p);
    int e = blockIdx.x * blockDim.x + threadIdx.x;
    if (e >= E) return;
    int d;
    if (is64) d = (int)((const long long*)p)[(size_t)E + e];
    else      d = ((const int*)p)[(size_t)E + e];
    atomicAdd(&g_cnt[d], 1);
}

// ---------------- scan / scatter ----------------
__global__ void k_scanA(int n) {
    __shared__ int sh[1024];
    int t = threadIdx.x;
    int idx = blockIdx.x * 1024 + t;
    int v = (idx < n) ? g_cnt[idx] : 0;
    sh[t] = v;
    __syncthreads();
#pragma unroll
    for (int off = 1; off < 1024; off <<= 1) {
        int add = (t >= off) ? sh[t - off] : 0;
        __syncthreads();
        sh[t] += add;
        __syncthreads();
    }
    int incl = sh[t];
    if (idx < n) g_rptr[idx] = incl - v;
    if (t == 1023) g_part[blockIdx.x] = incl;
}

__global__ void k_scanC(int n, int E) {
    __shared__ int bsum;
    int b = blockIdx.x;
    int npart = b >> 2;
    if (threadIdx.x < 32) {
        int acc = 0;
        for (int i = threadIdx.x; i < npart; i += 32) acc += g_part[i];
#pragma unroll
        for (int o = 16; o; o >>= 1) acc += __shfl_down_sync(0xffffffffu, acc, o);
        if (threadIdx.x == 0) bsum = acc;
    }
    __syncthreads();
    int idx = b * 256 + threadIdx.x;
    if (idx < n) {
        int r = g_rptr[idx] + bsum;
        g_rptr[idx] = r;
        g_cursor[idx] = r;
    }
    if (idx == 0) g_rptr[n] = E;
}

__global__ void k_scatter(const void* p, int E) {
    int is64 = detect_is64(p);
    int e = blockIdx.x * blockDim.x + threadIdx.x;
    if (e >= E) return;
    int s, d;
    if (is64) {
        const long long* q = (const long long*)p;
        s = (int)q[e];
        d = (int)q[(size_t)E + e];
    } else {
        const int* q = (const int*)p;
        s = q[e];
        d = q[(size_t)E + e];
    }
    int pos = atomicAdd(&g_cursor[d], 1);
    g_csr[pos] = s;
}

// ---------------- GEMM: G(fp16) = A @ W, BM=64, fp16 2-product -------------
// SCALE: epilogue multiplies row r by rsqrt(g_cnt[r]+1)  (dinv folding).
template <int NC, typename TIn, bool SCALE>
__global__ __launch_bounds__(256, 2) void k_gemm(
    const TIn* __restrict__ X, const __half* __restrict__ Ws,
    __half* __restrict__ G, int n, int ntiles)
{
    extern __shared__ char smem[];
    constexpr int PITCH = 272;
    constexpr int BM = 64;
    constexpr int AH = 0;
    constexpr int BH = AH + BM * PITCH;
    constexpr int BL = BH + NC * PITCH;
    constexpr int NF = NC / 32;

    uint32_t sb = smem_u32(smem);
    int tid = threadIdx.x;

    // ---- B once per CTA: W hi/lo fp16 (NC x 128 each) ----
    {
        constexpr int BU4 = NC * 128 * 2 / 16;
        const uint4* ws4 = (const uint4*)Ws;
#pragma unroll
        for (int r = 0; r < BU4 / 256; r++) {
            int li = tid + r * 256;
            int c = li >> 4;
            int ch = li & 15;
            *(uint4*)(smem + BH + c * PITCH + ch * 16) = ws4[li];
            *(uint4*)(smem + BL + c * PITCH + ch * 16) = ws4[BU4 + li];
        }
    }

    int wid = tid >> 5;
    int lane = tid & 31;
    int wm = wid & 1;
    int wn = wid >> 1;
    int m0 = wm * 32;
    int n0 = wn * (NC / 4);

    uint32_t a_addr0 = sb + AH + (uint32_t)(m0 + (lane & 15)) * PITCH + ((lane >> 4) * 16);
    uint32_t b_row   = (uint32_t)(n0 + (lane & 7) + ((lane >> 4) & 1) * 8);
    uint32_t b_addr0 = sb + BH + b_row * PITCH + (((lane >> 3) & 1) * 16);

    for (int tile = blockIdx.x; tile < ntiles; tile += gridDim.x) {
        int mbase = tile * BM;

        // ---- A prologue ----
        if constexpr (sizeof(TIn) == 4) {
            int ar = tid >> 2;
            int ak0 = (tid & 3) * 32;
            int row = mbase + ar;
            char* ap = smem + AH + ar * PITCH;
#pragma unroll
            for (int k = ak0; k < ak0 + 32; k += 4) {
                float4 v = make_float4(0.f, 0.f, 0.f, 0.f);
                if (row < n) v = *(const float4*)((const float*)X + (size_t)row * IN_DIM + k);
                __half2 p0 = __floats2half2_rn(v.x, v.y);
                __half2 p1 = __floats2half2_rn(v.z, v.w);
                uint2 u; u.x = *(uint32_t*)&p0; u.y = *(uint32_t*)&p1;
                *(uint2*)(ap + k * 2) = u;
            }
        } else {
#pragma unroll
            for (int r = 0; r < 4; r++) {
                int li = tid + r * 256;
                int row = li >> 4;
                int ch = li & 15;
                uint4 v = make_uint4(0, 0, 0, 0);
                if (mbase + row < n)
                    v = *(const uint4*)((const char*)((const __half*)X + (size_t)(mbase + row) * IN_DIM) + ch * 16);
                *(uint4*)(smem + AH + row * PITCH + ch * 16) = v;
            }
        }
        __syncthreads();

        float acc[2][NF][4];
#pragma unroll
        for (int mi = 0; mi < 2; mi++)
#pragma unroll
            for (int nf = 0; nf < NF; nf++)
#pragma unroll
                for (int q = 0; q < 4; q++) acc[mi][nf][q] = 0.0f;

#pragma unroll
        for (int ks = 0; ks < 8; ks++) {
            uint32_t koff = ks * 32;
            uint32_t a[2][4];
            ldsm4(a[0], a_addr0 + koff);
            ldsm4(a[1], a_addr0 + 16 * PITCH + koff);
            uint32_t bh[NF][2], bl[NF][2];
#pragma unroll
            for (int pr = 0; pr < NF / 2; pr++) {
                uint32_t r[4];
                ldsm4(r, b_addr0 + pr * 16 * PITCH + koff);
                bh[2 * pr][0] = r[0]; bh[2 * pr][1] = r[1];
                bh[2 * pr + 1][0] = r[2]; bh[2 * pr + 1][1] = r[3];
                ldsm4(r, b_addr0 + (BL - BH) + pr * 16 * PITCH + koff);
                bl[2 * pr][0] = r[0]; bl[2 * pr][1] = r[1];
                bl[2 * pr + 1][0] = r[2]; bl[2 * pr + 1][1] = r[3];
            }
#pragma unroll
            for (int mi = 0; mi < 2; mi++)
#pragma unroll
                for (int nf = 0; nf < NF; nf++) {
                    mma_f16(acc[mi][nf], a[mi], bh[nf]);
                    mma_f16(acc[mi][nf], a[mi], bl[nf]);
                }
        }

        // ---- epilogue: optional dinv scaling + fp16 stores ----
#pragma unroll
        for (int mi = 0; mi < 2; mi++) {
            int r0 = mbase + m0 + mi * 16 + (lane >> 2);
            float s0 = 1.0f, s1 = 1.0f;
            if (SCALE) {
                if (r0 < n)     s0 = rsqrtf((float)g_cnt[r0] + 1.0f);
                if (r0 + 8 < n) s1 = rsqrtf((float)g_cnt[r0 + 8] + 1.0f);
            }
#pragma unroll
            for (int nf = 0; nf < NF; nf++) {
                int col = n0 + nf * 8 + 2 * (lane & 3);
                if (r0 < n) {
                    __half2 v = __floats2half2_rn(acc[mi][nf][0] * s0, acc[mi][nf][1] * s0);
                    *(__half2*)(G + (size_t)r0 * NC + col) = v;
                }
                if (r0 + 8 < n) {
                    __half2 v = __floats2half2_rn(acc[mi][nf][2] * s1, acc[mi][nf][3] * s1);
                    *(__half2*)(G + (size_t)(r0 + 8) * NC + col) = v;
                }
            }
        }
        __syncthreads();
    }
}

// -------- aggregation over pre-scaled messages:
//   acc = sum_{j in N(i)} G[j] + G[i]       (G rows already carry dinv[src])
//   r = acc*dinv_i + bias; RELU optional; OUT_SCALE multiplies r by dinv_i
template <int NC, bool RELU, bool OUT_SCALE, typename OutT>
__global__ __launch_bounds__(256) void k_agg(
    const __half* __restrict__ G, const float* __restrict__ bias,
    OutT* __restrict__ OUT, int n)
{
    constexpr int V = NC / 32;
    constexpr int V2 = V / 2;
    int gw = (blockIdx.x * blockDim.x + threadIdx.x) >> 5;
    int lane = threadIdx.x & 31;
    if (gw >= n) return;

    float di = rsqrtf((float)g_cnt[gw] + 1.0f);

    float acc[V];
    {
        const __half2* ps = (const __half2*)(G + (size_t)gw * NC + lane * V);
#pragma unroll
        for (int q = 0; q < V2; q++) {
            float2 fv = __half22float2(ps[q]);
            acc[2 * q] = fv.x;
            acc[2 * q + 1] = fv.y;
        }
    }

    int s = g_rptr[gw], e = g_rptr[gw + 1];
    for (int base = s; base < e; base += 32) {
        int idx = base + lane;
        int sj = (idx < e) ? g_csr[idx] : 0;
        int m = e - base; if (m > 32) m = 32;
        int j = 0;
        for (; j + 4 <= m; j += 4) {
            int s0 = __shfl_sync(0xffffffffu, sj, j);
            int s1 = __shfl_sync(0xffffffffu, sj, j + 1);
            int s2 = __shfl_sync(0xffffffffu, sj, j + 2);
            int s3 = __shfl_sync(0xffffffffu, sj, j + 3);
            const __half2* p0 = (const __half2*)(G + (size_t)s0 * NC + lane * V);
            const __half2* p1 = (const __half2*)(G + (size_t)s1 * NC + lane * V);
            const __half2* p2 = (const __half2*)(G + (size_t)s2 * NC + lane * V);
            const __half2* p3 = (const __half2*)(G + (size_t)s3 * NC + lane * V);
#pragma unroll
            for (int q = 0; q < V2; q++) {
                float2 a = __half22float2(p0[q]);
                float2 b = __half22float2(p1[q]);
                float2 c = __half22float2(p2[q]);
                float2 d = __half22float2(p3[q]);
                acc[2 * q]     += (a.x + b.x) + (c.x + d.x);
                acc[2 * q + 1] += (a.y + b.y) + (c.y + d.y);
            }
        }
        for (; j < m; j++) {
            int s0 = __shfl_sync(0xffffffffu, sj, j);
            const __half2* p = (const __half2*)(G + (size_t)s0 * NC + lane * V);
#pragma unroll
            for (int q = 0; q < V2; q++) {
                float2 a = __half22float2(p[q]);
                acc[2 * q]     += a.x;
                acc[2 * q + 1] += a.y;
            }
        }
    }

    float bv[V];
#pragma unroll
    for (int q = 0; q < V2; q++) {
        float2 b = *(const float2*)(bias + lane * V + 2 * q);
        bv[2 * q] = b.x; bv[2 * q + 1] = b.y;
    }
    float r[V];
#pragma unroll
    for (int v = 0; v < V; v++) {
        r[v] = acc[v] * di + bv[v];
        if (RELU) r[v] = fmaxf(r[v], 0.0f);
        if (OUT_SCALE) r[v] *= di;
    }
    if constexpr (sizeof(OutT) == 2) {
        __half2* po = (__half2*)((__half*)OUT + (size_t)gw * NC + lane * V);
#pragma unroll
        for (int q = 0; q < V2; q++)
            po[q] = __floats2half2_rn(r[2 * q], r[2 * q + 1]);
    } else {
        float* po = (float*)OUT + (size_t)gw * NC + lane * V;
#pragma unroll
        for (int q = 0; q < V2; q++) {
            float2 o; o.x = r[2 * q]; o.y = r[2 * q + 1];
            *(float2*)(po + 2 * q) = o;
        }
    }
}

// ---------------- launch ----------------
extern "C" void kernel_launch(void* const* d_in, const int* in_sizes, int n_in,
                              void* d_out, int out_size)
{
    const float* x  = (const float*)d_in[0];
    const void*  ei = d_in[1];
    const float* W1 = (const float*)d_in[2];
    const float* b1 = (const float*)d_in[3];
    const float* W2 = (const float*)d_in[4];
    const float* b2 = (const float*)d_in[5];
    float* out = (float*)d_out;

    int n = in_sizes[0] / IN_DIM;
    int E = in_sizes[1] / 2;

    __half *g1p, *h1p, *g2p, *w1s, *w2s;
    cudaGetSymbolAddress((void**)&g1p, g_g1);
    cudaGetSymbolAddress((void**)&h1p, g_h1);
    cudaGetSymbolAddress((void**)&g2p, g_g2);
    cudaGetSymbolAddress((void**)&w1s, g_w1s);
    cudaGetSymbolAddress((void**)&w2s, g_w2s);

    const int smem1 = 64 * 272 + 2 * 128 * 272;   // 87040 -> 2 CTAs/SM
    const int smem2 = 64 * 272 + 2 * 64 * 272;    // 52224 -> 4 CTAs/SM
    cudaFuncSetAttribute((const void*)k_gemm<HID_DIM, float, true>,
                         cudaFuncAttributeMaxDynamicSharedMemorySize, smem1);
    cudaFuncSetAttribute((const void*)k_gemm<OUT_DIM, __half, false>,
                         cudaFuncAttributeMaxDynamicSharedMemorySize, smem2);

    // side stream + fork/join events (host objects, created once)
    static cudaStream_t s2 = nullptr;
    static cudaEvent_t evFork = nullptr, evJoin = nullptr;
    if (!s2) {
        cudaStreamCreateWithFlags(&s2, cudaStreamNonBlocking);
        cudaEventCreateWithFlags(&evFork, cudaEventDisableTiming);
        cudaEventCreateWithFlags(&evJoin, cudaEventDisableTiming);
    }

    int nb1024 = (n + 1023) / 1024;
    int ntiles = (n + 63) / 64;
    int pg1 = (ntiles < 296) ? ntiles : 296;
    int pg2 = (ntiles < 592) ? ntiles : 592;
    int igrid = (n > HID_DIM * IN_DIM + OUT_DIM * HID_DIM ? n
                 : HID_DIM * IN_DIM + OUT_DIM * HID_DIM);

    // main: init (zero cnt + split weights) -> convcnt (counts final)
    k_init<<<(igrid + 255) / 256, 256>>>(W1, W2, n);
    k_convcnt<<<(E + 255) / 256, 256>>>(ei, E);

    // fork: scan/scatter on s2, concurrent with gemm1 on main stream
    cudaEventRecord(evFork, 0);
    cudaStreamWaitEvent(s2, evFork, 0);
    k_scanA<<<nb1024, 1024, 0, s2>>>(n);
    k_scanC<<<(n + 255) / 256, 256, 0, s2>>>(n, E);
    k_scatter<<<(E + 255) / 256, 256, 0, s2>>>(ei, E);
    cudaEventRecord(evJoin, s2);

    // gemm1 with dinv-scaled epilogue (needs g_cnt only)
    k_gemm<HID_DIM, float, true><<<pg1, 256, smem1>>>(x, w1s, g1p, n, ntiles);

    // join: agg1 needs gemm1 (stream order) + CSR (event)
    cudaStreamWaitEvent(0, evJoin, 0);

    k_agg<HID_DIM, true, true, __half><<<(n * 32 + 255) / 256, 256>>>(g1p, b1, h1p, n);
    k_gemm<OUT_DIM, __half, false><<<pg2, 256, smem2>>>(h1p, w2s, g2p, n, ntiles);
    k_agg<OUT_DIM, false, false, float><<<(n * 32 + 255) / 256, 256>>>(g2p, b2, out, n);
}